// round 1
// baseline (speedup 1.0000x reference)
#include <cuda_runtime.h>

// Problem constants: b=8, dim=64, heads=2, H=W=256
#define NPIX 65536
#define NPAIR 32768   // pixels as float2 pairs

typedef unsigned long long u64;

// ---------------- scratch (device globals; allocation-free rule) ----------------
__device__ float g_qkv [100663296];   // [8][192][65536] after 1x1 conv
__device__ float g_qkvd[100663296];   // [8][192][65536] after depthwise 3x3
__device__ float g_inv [8 * 128];     // 1/max(||row||,eps) for q (0..63) and k (64..127)
__device__ float g_part[16 * 64 * 1024]; // attn partial sums [bh][chunk][32*32]
__device__ float g_P   [8 * 64 * 64];    // fused (W_proj * blockdiag(M)) per batch

// ---------------- f32x2 helpers (packed FFMA2: only reachable via PTX) ----------
__device__ __forceinline__ u64 pk2(float a, float b) {
    u64 r; asm("mov.b64 %0,{%1,%2};" : "=l"(r) : "f"(a), "f"(b)); return r;
}
__device__ __forceinline__ u64 fma2(u64 a, u64 b, u64 c) {
    u64 d; asm("fma.rn.f32x2 %0,%1,%2,%3;" : "=l"(d) : "l"(a), "l"(b), "l"(c)); return d;
}

// ---------------- K1 / K6: pointwise GEMM  out[oc][n] = sum_ic w[oc][ic]*in[ic][n] ----
// IC fixed = 64. Block: 64 oc x 128 pixels (64 pairs). 256 thr: 16 oc-groups x 16 px-groups,
// thread tile 4 oc x 4 pairs, f32x2 accumulators.
__global__ __launch_bounds__(256) void pw_gemm_kernel(
    const u64* __restrict__ in2, const float* __restrict__ wgt, u64* __restrict__ out2,
    long in_bs2, long out_bs2, int wgt_bs)
{
    __shared__ u64  xs[64 * 64];   // [ic][pair] 32 KB
    __shared__ float ws[64 * 64];  // [ic][oc]   16 KB
    const int b   = blockIdx.z;
    const int ocb = blockIdx.y * 64;
    const int px2 = blockIdx.x * 64;           // pair base
    const u64*   inb = in2 + (long)b * in_bs2 + px2;
    const float* wb  = wgt + (long)b * wgt_bs;
    const int tid = threadIdx.x;

    #pragma unroll
    for (int i = 0; i < 16; i++) {
        int li = tid + i * 256;                // 0..4095
        int ic = li >> 6;
        int lo = li & 63;
        xs[li] = inb[(long)ic * NPAIR + lo];
        ws[ic * 64 + lo] = wb[(ocb + lo) * 64 + ic];
    }
    __syncthreads();

    const int ob = (tid >> 4) * 4;   // local oc base (0..60)
    const int pb = (tid & 15) * 4;   // local pair base (0..60)
    u64 acc[4][4];
    #pragma unroll
    for (int i = 0; i < 4; i++)
        #pragma unroll
        for (int j = 0; j < 4; j++) acc[i][j] = 0ULL;

    #pragma unroll 8
    for (int ic = 0; ic < 64; ic++) {
        u64 xv[4]; float wv[4];
        #pragma unroll
        for (int j = 0; j < 4; j++) xv[j] = xs[ic * 64 + pb + j];
        #pragma unroll
        for (int i = 0; i < 4; i++) wv[i] = ws[ic * 64 + ob + i];
        #pragma unroll
        for (int i = 0; i < 4; i++) {
            u64 w2 = pk2(wv[i], wv[i]);
            #pragma unroll
            for (int j = 0; j < 4; j++) acc[i][j] = fma2(w2, xv[j], acc[i][j]);
        }
    }

    u64* ob2 = out2 + (long)b * out_bs2 + px2 + pb;
    #pragma unroll
    for (int i = 0; i < 4; i++)
        #pragma unroll
        for (int j = 0; j < 4; j++)
            ob2[(long)(ocb + ob + i) * NPAIR + j] = acc[i][j];
}

// ---------------- K2: depthwise 3x3, pad 1 (cross-correlation) ------------------
__global__ __launch_bounds__(256) void dw_kernel(const float* __restrict__ w_dw)
{
    __shared__ float s[10][258];
    const int b = blockIdx.z, ch = blockIdx.y, y0 = blockIdx.x * 8;
    const float* in  = g_qkv  + ((long)b * 192 + ch) * NPIX;
    float*       out = g_qkvd + ((long)b * 192 + ch) * NPIX;
    const int tid = threadIdx.x;

    #pragma unroll
    for (int r = 0; r < 10; r++) {
        int y = y0 - 1 + r;
        s[r][tid + 1] = (y >= 0 && y < 256) ? in[y * 256 + tid] : 0.f;
    }
    if (tid < 10) { s[tid][0] = 0.f; s[tid][257] = 0.f; }
    float w[9];
    #pragma unroll
    for (int i = 0; i < 9; i++) w[i] = w_dw[ch * 9 + i];
    __syncthreads();

    #pragma unroll
    for (int ry = 0; ry < 8; ry++) {
        float a = 0.f;
        #pragma unroll
        for (int dy = 0; dy < 3; dy++)
            #pragma unroll
            for (int dx = 0; dx < 3; dx++)
                a += w[dy * 3 + dx] * s[ry + dy][tid + dx];
        out[(y0 + ry) * 256 + tid] = a;
    }
}

// ---------------- K3: per-row sum of squares -> inverse L2 norm -----------------
__global__ __launch_bounds__(256) void sumsq_kernel()
{
    const int c = blockIdx.x, b = blockIdx.y;   // c in 0..127 (q then k channels)
    const float4* p = (const float4*)(g_qkvd + ((long)b * 192 + c) * NPIX);
    const int tid = threadIdx.x;
    float s = 0.f;
    #pragma unroll 4
    for (int i = tid; i < 16384; i += 256) {
        float4 v = p[i];
        s += v.x * v.x + v.y * v.y + v.z * v.z + v.w * v.w;
    }
    #pragma unroll
    for (int o = 16; o; o >>= 1) s += __shfl_xor_sync(0xffffffffu, s, o);
    __shared__ float sm[8];
    if ((tid & 31) == 0) sm[tid >> 5] = s;
    __syncthreads();
    if (tid == 0) {
        float t = 0.f;
        #pragma unroll
        for (int i = 0; i < 8; i++) t += sm[i];
        g_inv[b * 128 + c] = 1.f / fmaxf(sqrtf(t), 1e-12f);
    }
}

// ---------------- K4: attn partials  raw[c][d] = sum_n q[c][n]k[d][n] -----------
#define QST 129   // row stride: avoids bank conflicts for stride-4 row access
__global__ __launch_bounds__(256) void attn_kernel()
{
    __shared__ float qs[32 * QST];
    __shared__ float ks[32 * QST];
    const int cx = blockIdx.x, bh = blockIdx.y;
    const int b = bh >> 1, h = bh & 1;
    const float* qb = g_qkvd + ((long)b * 192 +        h * 32) * NPIX;
    const float* kb = g_qkvd + ((long)b * 192 + 64  +  h * 32) * NPIX;
    const int tid = threadIdx.x;
    const int ng = tid >> 6, ct = (tid >> 3) & 7, dt = tid & 7;

    float acc[4][4];
    #pragma unroll
    for (int i = 0; i < 4; i++)
        #pragma unroll
        for (int j = 0; j < 4; j++) acc[i][j] = 0.f;

    const int n_base = cx * 1024;
    for (int sc = 0; sc < 8; sc++) {
        const int n0 = n_base + sc * 128;
        if (sc) __syncthreads();
        #pragma unroll
        for (int i = 0; i < 4; i++) {
            int li = tid + i * 256;            // 0..1023
            int c = li >> 5, f4 = li & 31;
            float4 qv = *(const float4*)(qb + (long)c * NPIX + n0 + f4 * 4);
            float4 kv = *(const float4*)(kb + (long)c * NPIX + n0 + f4 * 4);
            float* qd = qs + c * QST + f4 * 4;
            float* kd = ks + c * QST + f4 * 4;
            qd[0] = qv.x; qd[1] = qv.y; qd[2] = qv.z; qd[3] = qv.w;
            kd[0] = kv.x; kd[1] = kv.y; kd[2] = kv.z; kd[3] = kv.w;
        }
        __syncthreads();
        const int nn0 = ng * 32;
        #pragma unroll 8
        for (int nn = nn0; nn < nn0 + 32; nn++) {
            float qv[4], kv[4];
            #pragma unroll
            for (int i = 0; i < 4; i++) qv[i] = qs[(ct * 4 + i) * QST + nn];
            #pragma unroll
            for (int j = 0; j < 4; j++) kv[j] = ks[(dt * 4 + j) * QST + nn];
            #pragma unroll
            for (int i = 0; i < 4; i++)
                #pragma unroll
                for (int j = 0; j < 4; j++) acc[i][j] += qv[i] * kv[j];
        }
    }

    __syncthreads();
    float* red = qs;   // reuse: 256*16 = 4096 <= 32*129
    #pragma unroll
    for (int i = 0; i < 4; i++)
        #pragma unroll
        for (int j = 0; j < 4; j++) red[tid * 16 + i * 4 + j] = acc[i][j];
    __syncthreads();
    if (tid < 64) {
        const int c2 = tid >> 3, d2 = tid & 7;
        #pragma unroll
        for (int i = 0; i < 4; i++)
            #pragma unroll
            for (int j = 0; j < 4; j++) {
                int t = i * 4 + j;
                float v = red[tid * 16 + t] + red[(tid + 64) * 16 + t]
                        + red[(tid + 128) * 16 + t] + red[(tid + 192) * 16 + t];
                g_part[(bh * 64 + cx) * 1024 + (c2 * 4 + i) * 32 + (d2 * 4 + j)] = v;
            }
    }
}

// ---------------- K5: topk-masked softmax x3, combine, build fused P ------------
__global__ __launch_bounds__(1024) void soft_kernel(
    const float* __restrict__ temp, const float* __restrict__ a1,
    const float* __restrict__ a2,  const float* __restrict__ a3,
    const float* __restrict__ wp)
{
    __shared__ float M[32 * 33];
    const int bh = blockIdx.x, b = bh >> 1, h = bh & 1;
    const int tid = threadIdx.x, c = tid >> 5, d = tid & 31;

    float raw = 0.f;
    const float* pp = g_part + bh * 65536 + c * 32 + d;
    #pragma unroll 8
    for (int p = 0; p < 64; p++) raw += pp[p * 1024];

    float v = raw * g_inv[b * 128 + h * 32 + c]
                  * g_inv[b * 128 + 64 + h * 32 + d] * temp[h];

    // rank with torch.topk tie-break (earlier index wins)
    int rank = 0;
    #pragma unroll
    for (int j = 0; j < 32; j++) {
        float vj = __shfl_sync(0xffffffffu, v, j);
        rank += (vj > v) || (vj == v && j < d);
    }
    float m = v;
    #pragma unroll
    for (int o = 16; o; o >>= 1) m = fmaxf(m, __shfl_xor_sync(0xffffffffu, m, o));
    float e  = expf(v - m);
    float e1 = rank < 16 ? e : 0.f;
    float e2 = rank < 21 ? e : 0.f;
    float e3 = rank < 24 ? e : 0.f;
    float s1 = e1, s2 = e2, s3 = e3;
    #pragma unroll
    for (int o = 16; o; o >>= 1) {
        s1 += __shfl_xor_sync(0xffffffffu, s1, o);
        s2 += __shfl_xor_sync(0xffffffffu, s2, o);
        s3 += __shfl_xor_sync(0xffffffffu, s3, o);
    }
    M[c * 33 + d] = e1 * (a1[0] / s1) + e2 * (a2[0] / s2) + e3 * (a3[0] / s3);
    __syncthreads();

    // P[b][oc][h*32+d] = sum_c wp[oc][h*32+c] * M[c][d]   (fuses out-einsum + proj)
    const int oc = tid >> 5, dd = tid & 31;
    float p0 = 0.f, p1 = 0.f;
    #pragma unroll
    for (int cc = 0; cc < 32; cc++) {
        float mm = M[cc * 33 + dd];
        p0 += wp[oc * 64 + h * 32 + cc] * mm;
        p1 += wp[(oc + 32) * 64 + h * 32 + cc] * mm;
    }
    g_P[b * 4096 + oc * 64 + h * 32 + dd]        = p0;
    g_P[b * 4096 + (oc + 32) * 64 + h * 32 + dd] = p1;
}

// ---------------- launch --------------------------------------------------------
extern "C" void kernel_launch(void* const* d_in, const int* in_sizes, int n_in,
                              void* d_out, int out_size)
{
    const float* x      = (const float*)d_in[0];
    const float* w_qkv  = (const float*)d_in[1];
    const float* w_dw   = (const float*)d_in[2];
    const float* w_proj = (const float*)d_in[3];
    const float* temp   = (const float*)d_in[4];
    const float* a1     = (const float*)d_in[5];
    const float* a2     = (const float*)d_in[6];
    const float* a3     = (const float*)d_in[7];

    void *pqkv, *pqkvd, *pP;
    cudaGetSymbolAddress(&pqkv,  g_qkv);
    cudaGetSymbolAddress(&pqkvd, g_qkvd);
    cudaGetSymbolAddress(&pP,    g_P);

    // K1: qkv 1x1 conv  (x[8,64,N] -> g_qkv[8,192,N])
    pw_gemm_kernel<<<dim3(512, 3, 8), 256>>>(
        (const u64*)x, w_qkv, (u64*)pqkv,
        64L * NPAIR, 192L * NPAIR, 0);
    // K2: depthwise 3x3 -> g_qkvd
    dw_kernel<<<dim3(32, 192, 8), 256>>>(w_dw);
    // K3: inverse L2 norms of q,k rows
    sumsq_kernel<<<dim3(128, 8), 256>>>();
    // K4: attn raw dot-product partials
    attn_kernel<<<dim3(64, 16), 256>>>();
    // K5: topk softmax x3 + combine + fused P
    soft_kernel<<<16, 1024>>>(temp, a1, a2, a3, w_proj);
    // K6: final = P @ V  (V = g_qkvd channels 128..191) -> d_out
    pw_gemm_kernel<<<dim3(512, 1, 8), 256>>>(
        (const u64*)pqkvd + 128L * NPAIR, (const float*)pP, (u64*)d_out,
        192L * NPAIR, 64L * NPAIR, 4096);
}